// round 1
// baseline (speedup 1.0000x reference)
#include <cuda_runtime.h>
#include <stdint.h>
#include <math.h>

#define THREADS 256
#define TILE    32
#define TPG     8      // tiles per group (per block)
#define GPB     8      // groups per batch: 8*8*32 = 2048 rows covered
#define LDIM    2048
#define BDIM    128

template<int NEMB>
struct Cfg {
    static constexpr int GEO = (NEMB == 4) ? 2 : 1;
    static constexpr int IN  = GEO + NEMB * 16;
    static constexpr int NROWS = LDIM - NEMB + 1;
    static constexpr int SMEM_FLOATS =
        IN * 128          // W1
        + 128 * 128       // W2
        + 128 + 128 + 128 // b1, b2, W3
        + 320             // emb (20x16)
        + TILE * IN       // x tile
        + TILE * 128      // h1 tile
        + 48              // seq slice (ints)
        + 4;              // block sum + pad
    static constexpr int SMEM_BYTES = SMEM_FLOATS * 4;
};

__global__ void zero_kernel(float* out, int n) {
    int i = blockIdx.x * blockDim.x + threadIdx.x;
    if (i < n) out[i] = 0.f;
}

template<int NEMB>
__global__ __launch_bounds__(THREADS, 1)
void mlp_energy_kernel(const float* __restrict__ R,
                       const int*   __restrict__ seq,
                       const float* __restrict__ emb,
                       const float* __restrict__ gW1, const float* __restrict__ gb1,
                       const float* __restrict__ gW2, const float* __restrict__ gb2,
                       const float* __restrict__ gW3, const float* __restrict__ gb3,
                       float* __restrict__ out)
{
    constexpr int GEO   = Cfg<NEMB>::GEO;
    constexpr int IN    = Cfg<NEMB>::IN;
    constexpr int NROWS = Cfg<NEMB>::NROWS;

    extern __shared__ float smem[];
    float* W1s  = smem;                       // IN*128
    float* W2s  = W1s + IN * 128;             // 128*128
    float* b1s  = W2s + 128 * 128;            // 128
    float* b2s  = b1s + 128;                  // 128
    float* W3s  = b2s + 128;                  // 128
    float* embs = W3s + 128;                  // 320
    float* xs   = embs + 320;                 // TILE*IN
    float* h1s  = xs + TILE * IN;             // TILE*128
    int*   seqs = (int*)(h1s + TILE * 128);   // 48 ints
    float* bsum = (float*)(seqs + 48);        // 1

    const int tid = threadIdx.x;

    // ---- stage weights / emb into shared ----
    for (int i = tid; i < IN * 128;  i += THREADS) W1s[i] = gW1[i];
    for (int i = tid; i < 128 * 128; i += THREADS) W2s[i] = gW2[i];
    if (tid < 128) { b1s[tid] = gb1[tid]; b2s[tid] = gb2[tid]; W3s[tid] = gW3[tid]; }
    for (int i = tid; i < 320; i += THREADS) embs[i] = emb[i];
    if (tid == 0) *bsum = 0.f;

    const int batch = blockIdx.x / GPB;
    const int group = blockIdx.x % GPB;
    const int wid  = tid >> 5;
    const int lane = tid & 31;
    const int r0 = wid * 4;   // rows of this warp within tile
    const int j0 = lane * 4;  // hidden columns of this lane
    const float b3r = gb3[0];

    const float* Rb   = R   + (size_t)batch * LDIM * 3;
    const int*   seqb = seq + (size_t)batch * LDIM;

    for (int tt = 0; tt < TPG; ++tt) {
        const int i0 = (group * TPG + tt) * TILE;

        __syncthreads();  // prev tile fully consumed (also covers weight staging)

        // ---- seq slice ----
        if (tid < TILE + NEMB - 1) {
            int idx = i0 + tid;
            seqs[tid] = (idx < LDIM) ? seqb[idx] : 0;
        }
        __syncthreads();

        // ---- geometry features (threads 0..31, one row each) ----
        if (tid < TILE) {
            const int r = tid;
            const int i = i0 + r;
            float* xrow = xs + r * IN;
            if (i < NROWS) {
                float p0x = Rb[i*3+0],     p0y = Rb[i*3+1],     p0z = Rb[i*3+2];
                float p1x = Rb[(i+1)*3+0], p1y = Rb[(i+1)*3+1], p1z = Rb[(i+1)*3+2];
                float d0x = p1x - p0x, d0y = p1y - p0y, d0z = p1z - p0z;
                if (NEMB == 2) {
                    xrow[0] = sqrtf(d0x*d0x + d0y*d0y + d0z*d0z);
                } else if (NEMB == 3) {
                    float p2x = Rb[(i+2)*3+0], p2y = Rb[(i+2)*3+1], p2z = Rb[(i+2)*3+2];
                    float d1x = p2x - p1x, d1y = p2y - p1y, d1z = p2z - p1z;
                    float dot01 = d0x*d1x + d0y*d1y + d0z*d1z;
                    float n0 = d0x*d0x + d0y*d0y + d0z*d0z;
                    float n1 = d1x*d1x + d1y*d1y + d1z*d1z;
                    float c  = -dot01 / (sqrtf(n0) * sqrtf(n1));
                    xrow[0] = fminf(1.f, fmaxf(-1.f, c));
                } else {
                    float p2x = Rb[(i+2)*3+0], p2y = Rb[(i+2)*3+1], p2z = Rb[(i+2)*3+2];
                    float p3x = Rb[(i+3)*3+0], p3y = Rb[(i+3)*3+1], p3z = Rb[(i+3)*3+2];
                    float d1x = p2x - p1x, d1y = p2y - p1y, d1z = p2z - p1z;
                    float d2x = p3x - p2x, d2y = p3y - p2y, d2z = p3z - p2z;
                    // n1 = d0 x d1 ; n2 = d1 x d2
                    float n1x = d0y*d1z - d0z*d1y;
                    float n1y = d0z*d1x - d0x*d1z;
                    float n1z = d0x*d1y - d0y*d1x;
                    float n2x = d1y*d2z - d1z*d2y;
                    float n2y = d1z*d2x - d1x*d2z;
                    float n2z = d1x*d2y - d1y*d2x;
                    float inv = rsqrtf(d1x*d1x + d1y*d1y + d1z*d1z);
                    float ux = d1x*inv, uy = d1y*inv, uz = d1z*inv;
                    // m1 = n1 x b2u
                    float m1x = n1y*uz - n1z*uy;
                    float m1y = n1z*ux - n1x*uz;
                    float m1z = n1x*uy - n1y*ux;
                    float yv = m1x*n2x + m1y*n2y + m1z*n2z;
                    float xv = n1x*n2x + n1y*n2y + n1z*n2z;
                    float rinv = rsqrtf(xv*xv + yv*yv);
                    xrow[0] = yv * rinv;   // sin(phi)
                    xrow[1] = xv * rinv;   // cos(phi)
                }
            } else {
                xrow[0] = 0.f;
                if (GEO == 2) xrow[1] = 0.f;
            }
        }

        // ---- embedding features (all threads) ----
        constexpr int EW = NEMB * 16;
        for (int e = tid; e < TILE * EW; e += THREADS) {
            int r   = e / EW;
            int rem = e - r * EW;
            float v = 0.f;
            if (i0 + r < NROWS) {
                int aa = seqs[r + (rem >> 4)];
                v = embs[aa * 16 + (rem & 15)];
            }
            xs[r * IN + GEO + rem] = v;
        }
        __syncthreads();

        // ---- layer 1: h1 = relu(x @ W1 + b1) ----
        float acc[4][4];
        #pragma unroll
        for (int i = 0; i < 4; ++i)
            #pragma unroll
            for (int c = 0; c < 4; ++c) acc[i][c] = 0.f;

        #pragma unroll 3
        for (int k = 0; k < IN; ++k) {
            float4 w = *(const float4*)(W1s + k * 128 + j0);
            #pragma unroll
            for (int i = 0; i < 4; ++i) {
                float xv = xs[(r0 + i) * IN + k];
                acc[i][0] = fmaf(xv, w.x, acc[i][0]);
                acc[i][1] = fmaf(xv, w.y, acc[i][1]);
                acc[i][2] = fmaf(xv, w.z, acc[i][2]);
                acc[i][3] = fmaf(xv, w.w, acc[i][3]);
            }
        }
        {
            float4 bb = *(const float4*)(b1s + j0);
            #pragma unroll
            for (int i = 0; i < 4; ++i) {
                float4 h;
                h.x = fmaxf(acc[i][0] + bb.x, 0.f);
                h.y = fmaxf(acc[i][1] + bb.y, 0.f);
                h.z = fmaxf(acc[i][2] + bb.z, 0.f);
                h.w = fmaxf(acc[i][3] + bb.w, 0.f);
                *(float4*)(h1s + (r0 + i) * 128 + j0) = h;
            }
        }
        __syncthreads();

        // ---- layer 2: h2 = relu(h1 @ W2 + b2), fused with layer 3 ----
        #pragma unroll
        for (int i = 0; i < 4; ++i)
            #pragma unroll
            for (int c = 0; c < 4; ++c) acc[i][c] = 0.f;

        #pragma unroll 4
        for (int k = 0; k < 128; ++k) {
            float4 w = *(const float4*)(W2s + k * 128 + j0);
            #pragma unroll
            for (int i = 0; i < 4; ++i) {
                float hv = h1s[(r0 + i) * 128 + k];
                acc[i][0] = fmaf(hv, w.x, acc[i][0]);
                acc[i][1] = fmaf(hv, w.y, acc[i][1]);
                acc[i][2] = fmaf(hv, w.z, acc[i][2]);
                acc[i][3] = fmaf(hv, w.w, acc[i][3]);
            }
        }

        // ---- epilogue: relu + dot with W3, warp-reduce per row ----
        float4 b2v = *(const float4*)(b2s + j0);
        float4 w3v = *(const float4*)(W3s + j0);
        float p[4];
        #pragma unroll
        for (int i = 0; i < 4; ++i) {
            float s;
            s  = fmaxf(acc[i][0] + b2v.x, 0.f) * w3v.x;
            s += fmaxf(acc[i][1] + b2v.y, 0.f) * w3v.y;
            s += fmaxf(acc[i][2] + b2v.z, 0.f) * w3v.z;
            s += fmaxf(acc[i][3] + b2v.w, 0.f) * w3v.w;
            p[i] = s;
        }
        #pragma unroll
        for (int off = 16; off; off >>= 1) {
            #pragma unroll
            for (int i = 0; i < 4; ++i)
                p[i] += __shfl_down_sync(0xffffffffu, p[i], off);
        }
        if (lane == 0) {
            float s = 0.f;
            #pragma unroll
            for (int i = 0; i < 4; ++i)
                if (i0 + r0 + i < NROWS) s += p[i] + b3r;
            atomicAdd(bsum, s);
        }
    }

    __syncthreads();
    if (tid == 0) atomicAdd(&out[batch], *bsum);
}

extern "C" void kernel_launch(void* const* d_in, const int* in_sizes, int n_in,
                              void* d_out, int out_size) {
    const float* R   = (const float*)d_in[0];
    const int*   seq = (const int*)d_in[1];
    const float* emb = (const float*)d_in[2];
    const float* fl[6]; const float* ft[6]; const float* fp[6];
    for (int i = 0; i < 6; ++i) {
        fl[i] = (const float*)d_in[3 + i];
        ft[i] = (const float*)d_in[9 + i];
        fp[i] = (const float*)d_in[15 + i];
    }
    float* out = (float*)d_out;

    cudaFuncSetAttribute(mlp_energy_kernel<2>,
        cudaFuncAttributeMaxDynamicSharedMemorySize, Cfg<2>::SMEM_BYTES);
    cudaFuncSetAttribute(mlp_energy_kernel<3>,
        cudaFuncAttributeMaxDynamicSharedMemorySize, Cfg<3>::SMEM_BYTES);
    cudaFuncSetAttribute(mlp_energy_kernel<4>,
        cudaFuncAttributeMaxDynamicSharedMemorySize, Cfg<4>::SMEM_BYTES);

    zero_kernel<<<1, 256>>>(out, out_size);

    dim3 grid(BDIM * GPB);
    mlp_energy_kernel<2><<<grid, THREADS, Cfg<2>::SMEM_BYTES>>>(
        R, seq, emb, fl[0], fl[1], fl[2], fl[3], fl[4], fl[5], out);
    mlp_energy_kernel<3><<<grid, THREADS, Cfg<3>::SMEM_BYTES>>>(
        R, seq, emb, ft[0], ft[1], ft[2], ft[3], ft[4], ft[5], out);
    mlp_energy_kernel<4><<<grid, THREADS, Cfg<4>::SMEM_BYTES>>>(
        R, seq, emb, fp[0], fp[1], fp[2], fp[3], fp[4], fp[5], out);
}

// round 2
// speedup vs baseline: 1.8568x; 1.8568x over previous
#include <cuda_runtime.h>
#include <stdint.h>
#include <math.h>

#define THREADS 512
#define TILE    64
#define TPG     4      // tiles per block
#define GPB     8      // blocks per batch: 8*4*64 = 2048 rows covered
#define LDIM    2048
#define BDIM    128

template<int NEMB>
struct Cfg {
    static constexpr int GEO = (NEMB == 4) ? 2 : 1;
    static constexpr int IN  = GEO + NEMB * 16;
    static constexpr int XST = (IN + 3) & ~3;    // padded x row stride (floats)
    static constexpr int NROWS = LDIM - NEMB + 1;
    static constexpr int SMEM_FLOATS =
        XST * 128         // W1 (zero-padded rows)
        + 128 * 128       // W2
        + 128 + 128 + 128 // b1, b2, W3
        + 320             // emb (20x16)
        + TILE * XST      // x tile (padded)
        + TILE * 128      // h1 tile
        + 68              // seq slice (ints)
        + 4;              // block sum + pad
    static constexpr int SMEM_BYTES = SMEM_FLOATS * 4;
};

__global__ void zero_kernel(float* out, int n) {
    int i = blockIdx.x * blockDim.x + threadIdx.x;
    if (i < n) out[i] = 0.f;
}

template<int NEMB>
__global__ __launch_bounds__(THREADS, 1)
void mlp_energy_kernel(const float* __restrict__ R,
                       const int*   __restrict__ seq,
                       const float* __restrict__ emb,
                       const float* __restrict__ gW1, const float* __restrict__ gb1,
                       const float* __restrict__ gW2, const float* __restrict__ gb2,
                       const float* __restrict__ gW3, const float* __restrict__ gb3,
                       float* __restrict__ out)
{
    constexpr int GEO   = Cfg<NEMB>::GEO;
    constexpr int IN    = Cfg<NEMB>::IN;
    constexpr int XST   = Cfg<NEMB>::XST;
    constexpr int NROWS = Cfg<NEMB>::NROWS;

    extern __shared__ float smem[];
    float* W1s  = smem;                       // XST*128 (zero padded)
    float* W2s  = W1s + XST * 128;            // 128*128
    float* b1s  = W2s + 128 * 128;            // 128
    float* b2s  = b1s + 128;                  // 128
    float* W3s  = b2s + 128;                  // 128
    float* embs = W3s + 128;                  // 320
    float* xs   = embs + 320;                 // TILE*XST
    float* h1s  = xs + TILE * XST;            // TILE*128
    int*   seqs = (int*)(h1s + TILE * 128);   // 68 ints
    float* bsum = (float*)(seqs + 68);        // 1

    const int tid = threadIdx.x;

    // ---- stage weights / emb into shared (pad W1 rows IN..XST with zeros) ----
    for (int i = tid; i < XST * 128; i += THREADS)
        W1s[i] = (i < IN * 128) ? gW1[i] : 0.f;
    for (int i = tid; i < 128 * 128; i += THREADS) W2s[i] = gW2[i];
    if (tid < 128) { b1s[tid] = gb1[tid]; b2s[tid] = gb2[tid]; W3s[tid] = gW3[tid]; }
    for (int i = tid; i < 320; i += THREADS) embs[i] = emb[i];
    if (tid == 0) *bsum = 0.f;

    // zero x-tile padding columns once (they are never overwritten)
    constexpr int PAD = XST - IN;
    for (int i = tid; i < TILE * PAD; i += THREADS) {
        int r = i / PAD, c = i - r * PAD;
        xs[r * XST + IN + c] = 0.f;
    }

    const int batch = blockIdx.x / GPB;
    const int group = blockIdx.x % GPB;
    const int wid  = tid >> 5;
    const int lane = tid & 31;
    const int r0 = wid * 4;   // rows of this warp within tile (16 warps * 4 = 64)
    const int j0 = lane * 4;  // hidden columns of this lane
    const float b3r = gb3[0];

    const float* Rb   = R   + (size_t)batch * LDIM * 3;
    const int*   seqb = seq + (size_t)batch * LDIM;

    for (int tt = 0; tt < TPG; ++tt) {
        const int i0 = (group * TPG + tt) * TILE;

        __syncthreads();  // prev tile fully consumed (also covers staging)

        // ---- seq slice ----
        if (tid < TILE + NEMB - 1) {
            int idx = i0 + tid;
            seqs[tid] = (idx < LDIM) ? seqb[idx] : 0;
        }
        __syncthreads();

        // ---- geometry features (threads 0..63, one row each) ----
        if (tid < TILE) {
            const int r = tid;
            const int i = i0 + r;
            float* xrow = xs + r * XST;
            if (i < NROWS) {
                float p0x = Rb[i*3+0],     p0y = Rb[i*3+1],     p0z = Rb[i*3+2];
                float p1x = Rb[(i+1)*3+0], p1y = Rb[(i+1)*3+1], p1z = Rb[(i+1)*3+2];
                float d0x = p1x - p0x, d0y = p1y - p0y, d0z = p1z - p0z;
                if (NEMB == 2) {
                    xrow[0] = sqrtf(d0x*d0x + d0y*d0y + d0z*d0z);
                } else if (NEMB == 3) {
                    float p2x = Rb[(i+2)*3+0], p2y = Rb[(i+2)*3+1], p2z = Rb[(i+2)*3+2];
                    float d1x = p2x - p1x, d1y = p2y - p1y, d1z = p2z - p1z;
                    float dot01 = d0x*d1x + d0y*d1y + d0z*d1z;
                    float n0 = d0x*d0x + d0y*d0y + d0z*d0z;
                    float n1 = d1x*d1x + d1y*d1y + d1z*d1z;
                    float c  = -dot01 / (sqrtf(n0) * sqrtf(n1));
                    xrow[0] = fminf(1.f, fmaxf(-1.f, c));
                } else {
                    float p2x = Rb[(i+2)*3+0], p2y = Rb[(i+2)*3+1], p2z = Rb[(i+2)*3+2];
                    float p3x = Rb[(i+3)*3+0], p3y = Rb[(i+3)*3+1], p3z = Rb[(i+3)*3+2];
                    float d1x = p2x - p1x, d1y = p2y - p1y, d1z = p2z - p1z;
                    float d2x = p3x - p2x, d2y = p3y - p2y, d2z = p3z - p2z;
                    float n1x = d0y*d1z - d0z*d1y;
                    float n1y = d0z*d1x - d0x*d1z;
                    float n1z = d0x*d1y - d0y*d1x;
                    float n2x = d1y*d2z - d1z*d2y;
                    float n2y = d1z*d2x - d1x*d2z;
                    float n2z = d1x*d2y - d1y*d2x;
                    float inv = rsqrtf(d1x*d1x + d1y*d1y + d1z*d1z);
                    float ux = d1x*inv, uy = d1y*inv, uz = d1z*inv;
                    float m1x = n1y*uz - n1z*uy;
                    float m1y = n1z*ux - n1x*uz;
                    float m1z = n1x*uy - n1y*ux;
                    float yv = m1x*n2x + m1y*n2y + m1z*n2z;
                    float xv = n1x*n2x + n1y*n2y + n1z*n2z;
                    float rinv = rsqrtf(xv*xv + yv*yv);
                    xrow[0] = yv * rinv;   // sin(phi)
                    xrow[1] = xv * rinv;   // cos(phi)
                }
            } else {
                xrow[0] = 0.f;
                if (GEO == 2) xrow[1] = 0.f;
            }
        }

        // ---- embedding features ----
        constexpr int EW = NEMB * 16;
        for (int e = tid; e < TILE * EW; e += THREADS) {
            int r   = e / EW;
            int rem = e - r * EW;
            float v = 0.f;
            if (i0 + r < NROWS) {
                int aa = seqs[r + (rem >> 4)];
                v = embs[aa * 16 + (rem & 15)];
            }
            xs[r * XST + GEO + rem] = v;
        }
        __syncthreads();

        // ---- layer 1: h1 = relu(x @ W1 + b1), vectorized over k ----
        float acc[4][4];
        #pragma unroll
        for (int i = 0; i < 4; ++i)
            #pragma unroll
            for (int c = 0; c < 4; ++c) acc[i][c] = 0.f;

        #pragma unroll 2
        for (int k = 0; k < XST; k += 4) {
            float xv[4][4];
            #pragma unroll
            for (int i = 0; i < 4; ++i) {
                float4 t = *(const float4*)(xs + (r0 + i) * XST + k);
                xv[i][0] = t.x; xv[i][1] = t.y; xv[i][2] = t.z; xv[i][3] = t.w;
            }
            #pragma unroll
            for (int kk = 0; kk < 4; ++kk) {
                float4 w = *(const float4*)(W1s + (k + kk) * 128 + j0);
                #pragma unroll
                for (int i = 0; i < 4; ++i) {
                    acc[i][0] = fmaf(xv[i][kk], w.x, acc[i][0]);
                    acc[i][1] = fmaf(xv[i][kk], w.y, acc[i][1]);
                    acc[i][2] = fmaf(xv[i][kk], w.z, acc[i][2]);
                    acc[i][3] = fmaf(xv[i][kk], w.w, acc[i][3]);
                }
            }
        }
        {
            float4 bb = *(const float4*)(b1s + j0);
            #pragma unroll
            for (int i = 0; i < 4; ++i) {
                float4 h;
                h.x = fmaxf(acc[i][0] + bb.x, 0.f);
                h.y = fmaxf(acc[i][1] + bb.y, 0.f);
                h.z = fmaxf(acc[i][2] + bb.z, 0.f);
                h.w = fmaxf(acc[i][3] + bb.w, 0.f);
                *(float4*)(h1s + (r0 + i) * 128 + j0) = h;
            }
        }
        __syncthreads();

        // ---- layer 2: relu(h1 @ W2 + b2) fused with layer-3 dot ----
        #pragma unroll
        for (int i = 0; i < 4; ++i)
            #pragma unroll
            for (int c = 0; c < 4; ++c) acc[i][c] = 0.f;

        #pragma unroll 2
        for (int k = 0; k < 128; k += 4) {
            float hv[4][4];
            #pragma unroll
            for (int i = 0; i < 4; ++i) {
                float4 t = *(const float4*)(h1s + (r0 + i) * 128 + k);
                hv[i][0] = t.x; hv[i][1] = t.y; hv[i][2] = t.z; hv[i][3] = t.w;
            }
            #pragma unroll
            for (int kk = 0; kk < 4; ++kk) {
                float4 w = *(const float4*)(W2s + (k + kk) * 128 + j0);
                #pragma unroll
                for (int i = 0; i < 4; ++i) {
                    acc[i][0] = fmaf(hv[i][kk], w.x, acc[i][0]);
                    acc[i][1] = fmaf(hv[i][kk], w.y, acc[i][1]);
                    acc[i][2] = fmaf(hv[i][kk], w.z, acc[i][2]);
                    acc[i][3] = fmaf(hv[i][kk], w.w, acc[i][3]);
                }
            }
        }

        // ---- epilogue: relu + dot with W3, warp-reduce per row ----
        float4 b2v = *(const float4*)(b2s + j0);
        float4 w3v = *(const float4*)(W3s + j0);
        float p[4];
        #pragma unroll
        for (int i = 0; i < 4; ++i) {
            float s;
            s  = fmaxf(acc[i][0] + b2v.x, 0.f) * w3v.x;
            s += fmaxf(acc[i][1] + b2v.y, 0.f) * w3v.y;
            s += fmaxf(acc[i][2] + b2v.z, 0.f) * w3v.z;
            s += fmaxf(acc[i][3] + b2v.w, 0.f) * w3v.w;
            p[i] = s;
        }
        #pragma unroll
        for (int off = 16; off; off >>= 1) {
            #pragma unroll
            for (int i = 0; i < 4; ++i)
                p[i] += __shfl_down_sync(0xffffffffu, p[i], off);
        }
        if (lane == 0) {
            float s = 0.f;
            #pragma unroll
            for (int i = 0; i < 4; ++i)
                if (i0 + r0 + i < NROWS) s += p[i] + b3r;
            atomicAdd(bsum, s);
        }
    }

    __syncthreads();
    if (tid == 0) atomicAdd(&out[batch], *bsum);
}

extern "C" void kernel_launch(void* const* d_in, const int* in_sizes, int n_in,
                              void* d_out, int out_size) {
    const float* R   = (const float*)d_in[0];
    const int*   seq = (const int*)d_in[1];
    const float* emb = (const float*)d_in[2];
    const float* fl[6]; const float* ft[6]; const float* fp[6];
    for (int i = 0; i < 6; ++i) {
        fl[i] = (const float*)d_in[3 + i];
        ft[i] = (const float*)d_in[9 + i];
        fp[i] = (const float*)d_in[15 + i];
    }
    float* out = (float*)d_out;

    cudaFuncSetAttribute(mlp_energy_kernel<2>,
        cudaFuncAttributeMaxDynamicSharedMemorySize, Cfg<2>::SMEM_BYTES);
    cudaFuncSetAttribute(mlp_energy_kernel<3>,
        cudaFuncAttributeMaxDynamicSharedMemorySize, Cfg<3>::SMEM_BYTES);
    cudaFuncSetAttribute(mlp_energy_kernel<4>,
        cudaFuncAttributeMaxDynamicSharedMemorySize, Cfg<4>::SMEM_BYTES);

    zero_kernel<<<1, 256>>>(out, out_size);

    dim3 grid(BDIM * GPB);
    mlp_energy_kernel<2><<<grid, THREADS, Cfg<2>::SMEM_BYTES>>>(
        R, seq, emb, fl[0], fl[1], fl[2], fl[3], fl[4], fl[5], out);
    mlp_energy_kernel<3><<<grid, THREADS, Cfg<3>::SMEM_BYTES>>>(
        R, seq, emb, ft[0], ft[1], ft[2], ft[3], ft[4], ft[5], out);
    mlp_energy_kernel<4><<<grid, THREADS, Cfg<4>::SMEM_BYTES>>>(
        R, seq, emb, fp[0], fp[1], fp[2], fp[3], fp[4], fp[5], out);
}